// round 4
// baseline (speedup 1.0000x reference)
#include <cuda_runtime.h>
#include <math_constants.h>

#define B      64
#define C      2048
#define FM     14
#define NPIX   196
#define NCHUNK 16
#define CCHUNK 128   // C / NCHUNK
#define TW     837

// scratch (no cudaMalloc allowed); zero-initialized at module load
__device__ float    g_partial[NCHUNK * B * NPIX];
__device__ unsigned g_cnt[B];

__constant__ int d_RH[11]   = {4,3,5,6,5,7,8,6,10,7,9};
__constant__ int d_RW[11]   = {4,5,3,6,7,5,8,10,6,9,7};
__constant__ int d_WOFF[12] = {0,121,241,361,442,522,602,651,696,741,789,837};
__constant__ int d_GOFF[3]  = {0, 361, 602};
__constant__ int d_GW[3]    = {361, 241, 235};
__constant__ int d_GN[3]    = {3, 2, 1};
__constant__ int d_GSLOT[3] = {0, 3, 5};

// ---------------------------------------------------------------------------
// Fused kernel: grid (NCHUNK, B), block 196.
// Phase 1: channel-chunk reduction (HBM-bound, ~8 TB/s).
// Phase 2: last block per batch runs the whole epilogue (SAT + scores + NMS).
// Output layout (fp32): [B*6 indices][B*6 scores][B*837 all_scores]
// ---------------------------------------------------------------------------
__global__ void __launch_bounds__(196) appm_fused_kernel(const float* __restrict__ x,
                                                         float* __restrict__ out)
{
    const int chunk = blockIdx.x;
    const int b     = blockIdx.y;
    const int t     = threadIdx.x;
    const int q     = t % 49;
    const int cw    = t / 49;
    const int lane  = t & 31;
    const int wid   = t >> 5;

    __shared__ float  s_red[NPIX];
    __shared__ int    s_last;
    // epilogue shared state
    __shared__ float  y[NPIX];
    __shared__ double SAT[FM + 1][FM + 1];
    __shared__ float  sc[TW];
    __shared__ int    wmeta[TW];           // i | j<<4 | rh<<8 | rw<<12
    __shared__ unsigned char valid[TW];

    // ================= Phase 1: reduce =================
    {
        const float4* base = reinterpret_cast<const float4*>(x)
                           + ((size_t)b * C + (size_t)chunk * CCHUNK) * 49;
        float4 acc = make_float4(0.f, 0.f, 0.f, 0.f);
#pragma unroll 8
        for (int c = cw; c < CCHUNK; c += 4) {
            float4 v = __ldcs(base + (size_t)c * 49 + q);
            acc.x += v.x; acc.y += v.y; acc.z += v.z; acc.w += v.w;
        }
        if (t < NPIX) s_red[t] = 0.f;
        __syncthreads();
        atomicAdd(&s_red[q * 4 + 0], acc.x);
        atomicAdd(&s_red[q * 4 + 1], acc.y);
        atomicAdd(&s_red[q * 4 + 2], acc.z);
        atomicAdd(&s_red[q * 4 + 3], acc.w);
        __syncthreads();
        if (t < NPIX)
            g_partial[(chunk * B + b) * NPIX + t] = s_red[t];
    }

    // ================= last-block election =================
    __syncthreads();                     // all partial stores issued
    if (t == 0) {
        __threadfence();                 // make them device-visible
        const unsigned old = atomicAdd(&g_cnt[b], 1u);
        s_last = (old == NCHUNK - 1) ? 1 : 0;
    }
    __syncthreads();
    if (!s_last) return;

    // ================= Phase 2: epilogue (one block per batch) ============
    if (t == 0) g_cnt[b] = 0;            // reset for next graph replay

    if (t < NPIX) {
        float acc = 0.f;
#pragma unroll
        for (int ch = 0; ch < NCHUNK; ch++)
            acc += g_partial[(ch * B + b) * NPIX + t];
        y[t] = acc;
    }
    if (t < FM + 1) { SAT[0][t] = 0.0; SAT[t][0] = 0.0; }
    __syncthreads();

    // integral image in double (matches reference to ~2e-7)
    if (t < FM) {
        double r = 0.0;
#pragma unroll
        for (int j = 0; j < FM; j++) {
            r += (double)y[t * FM + j];
            SAT[t + 1][j + 1] = r;
        }
    }
    __syncthreads();
    if (t < FM) {
        double r = 0.0;
#pragma unroll
        for (int i = 1; i <= FM; i++) {
            r += SAT[i][t + 1];
            SAT[i][t + 1] = r;
        }
    }
    __syncthreads();

    // all 837 window scores + packed meta
    for (int w = t; w < TW; w += 196) {
        int r = 0;
#pragma unroll
        for (int k = 1; k < 11; k++) r += (w >= d_WOFF[k]);
        const int loc = w - d_WOFF[r];
        const int rh  = d_RH[r], rw = d_RW[r];
        const int nw  = FM - rw + 1;
        const int i   = loc / nw, j = loc % nw;
        const float s = (float)(SAT[i + rh][j + rw] - SAT[i][j + rw]
                              - SAT[i + rh][j]      + SAT[i][j]);
        const float sv = s / (float)(rh * rw);
        sc[w]    = sv;
        wmeta[w] = i | (j << 4) | (rh << 8) | (rw << 12);
        valid[w] = 1;
        out[2 * B * 6 + (size_t)b * TW + w] = sv;      // all_scores
    }
    __syncthreads();

    if (wid >= 3) return;                // warps 0..2 run one NMS group each

    const int g     = wid;
    const int goff  = d_GOFF[g];
    const int W     = d_GW[g];
    const int nsel  = d_GN[g];
    const int slot0 = d_GSLOT[g];

    int last = 0;
    for (int step = 0; step < nsel; step++) {
        // scan + argmax (first-index tie-break = jnp.argmax)
        float bs = -CUDART_INF_F;
        int   bi = 0x7fffffff;
        for (int w = lane; w < W; w += 32) {
            if (valid[goff + w]) {
                const float s = sc[goff + w];
                if (s > bs) { bs = s; bi = w; }
            }
        }
#pragma unroll
        for (int o = 16; o > 0; o >>= 1) {
            const float s2 = __shfl_xor_sync(0xffffffffu, bs, o);
            const int   i2 = __shfl_xor_sync(0xffffffffu, bi, o);
            if (s2 > bs || (s2 == bs && i2 < bi)) { bs = s2; bi = i2; }
        }
        const bool anyv = bs > -CUDART_INF_F;
        const int  idx  = anyv ? bi : last;            // fallback: repeat last

        if (lane == 0) {
            out[(size_t)b * 6 + slot0 + step]         = (float)(goff + idx);
            out[B * 6 + (size_t)b * 6 + slot0 + step] = sc[goff + idx];
        }

        if (anyv) {
            const int  m   = wmeta[goff + idx];        // uniform across warp
            const float sx0 = (float)(((m >> 4) & 15) * 32);
            const float sy0 = (float)((m & 15) * 32);
            const float sx1 = (float)((((m >> 4) & 15) + ((m >> 12) & 15)) * 32 - 1);
            const float sy1 = (float)(((m & 15) + ((m >> 8) & 15)) * 32 - 1);
            const float sarea = (sx1 - sx0 + 1.f) * (sy1 - sy0 + 1.f);
            __syncwarp();
            for (int w = lane; w < W; w += 32) {
                if (valid[goff + w]) {
                    const int m2 = wmeta[goff + w];
                    const float x0 = (float)(((m2 >> 4) & 15) * 32);
                    const float y0c = (float)((m2 & 15) * 32);
                    const float x1 = (float)((((m2 >> 4) & 15) + ((m2 >> 12) & 15)) * 32 - 1);
                    const float y1c = (float)(((m2 & 15) + ((m2 >> 8) & 15)) * 32 - 1);
                    const float lx = fmaxf(x0, sx0);
                    const float ly = fmaxf(y0c, sy0);
                    const float rx = fminf(x1, sx1);
                    const float ry = fminf(y1c, sy1);
                    const float wx = rx - lx + 1.f;
                    const float wy = ry - ly + 1.f;
                    const float inter = (wx < 0.f || wy < 0.f) ? 0.f : wx * wy;
                    const float area  = (x1 - x0 + 1.f) * (y1c - y0c + 1.f);
                    const float iou   = inter / (area + sarea - inter);
                    if (iou > 0.25f) valid[goff + w] = 0;   // self-IoU=1 clears idx
                }
            }
            __syncwarp();
        }
        last = idx;
    }
}

extern "C" void kernel_launch(void* const* d_in, const int* in_sizes, int n_in,
                              void* d_out, int out_size)
{
    const float* x = (const float*)d_in[0];
    float* out = (float*)d_out;
    appm_fused_kernel<<<dim3(NCHUNK, B), 196>>>(x, out);
}

// round 5
// speedup vs baseline: 1.2901x; 1.2901x over previous
#include <cuda_runtime.h>
#include <math_constants.h>

#define B      64
#define C      2048
#define FM     14
#define NPIX   196
#define NCHUNK 16
#define CCHUNK 128   // C / NCHUNK
#define TW     837

// scratch for per-chunk partial channel sums (no cudaMalloc allowed)
__device__ float g_partial[NCHUNK * B * NPIX];

__constant__ int d_RH[11]   = {4,3,5,6,5,7,8,6,10,7,9};
__constant__ int d_RW[11]   = {4,5,3,6,7,5,8,10,6,9,7};
__constant__ int d_WOFF[12] = {0,121,241,361,442,522,602,651,696,741,789,837};
__constant__ int d_GR0[3]   = {0, 3, 6};
__constant__ int d_GOFF[3]  = {0, 361, 602};
__constant__ int d_GW[3]    = {361, 241, 235};
__constant__ int d_GN[3]    = {3, 2, 1};
__constant__ int d_GSLOT[3] = {0, 3, 5};

// ---------------------------------------------------------------------------
// Kernel 1: channel-chunk reduction.  grid = (NCHUNK, B), block = 196.
// Measured ~8.2 TB/s — at the HBM/LTS cap; unchanged.
// ---------------------------------------------------------------------------
__global__ void __launch_bounds__(196) appm_reduce_kernel(const float* __restrict__ x)
{
    const int chunk = blockIdx.x;
    const int b     = blockIdx.y;
    const int t     = threadIdx.x;
    const int q     = t % 49;
    const int cw    = t / 49;

    const float4* base = reinterpret_cast<const float4*>(x)
                       + ((size_t)b * C + (size_t)chunk * CCHUNK) * 49;

    float4 acc = make_float4(0.f, 0.f, 0.f, 0.f);
#pragma unroll 8
    for (int c = cw; c < CCHUNK; c += 4) {
        float4 v = __ldcs(base + (size_t)c * 49 + q);
        acc.x += v.x; acc.y += v.y; acc.z += v.z; acc.w += v.w;
    }

    __shared__ float s[NPIX];
    if (t < NPIX) s[t] = 0.f;
    __syncthreads();
    atomicAdd(&s[q * 4 + 0], acc.x);
    atomicAdd(&s[q * 4 + 1], acc.y);
    atomicAdd(&s[q * 4 + 2], acc.z);
    atomicAdd(&s[q * 4 + 3], acc.w);
    __syncthreads();
    if (t < NPIX)
        g_partial[(chunk * B + b) * NPIX + t] = s[t];
}

// ---------------------------------------------------------------------------
// Kernel 2: per-(batch, group) scores + greedy NMS.  grid = (B, 3), block 256.
// All-float SAT (reference computes scores in f32 anyway; deviation ~1e-6).
// Output layout (fp32): [B*6 indices][B*6 scores][B*837 all_scores]
// ---------------------------------------------------------------------------
__global__ void __launch_bounds__(256) appm_nms_kernel(float* __restrict__ out)
{
    const int b    = blockIdx.x;
    const int g    = blockIdx.y;
    const int tid  = threadIdx.x;
    const int lane = tid & 31;
    const int wid  = tid >> 5;

    const int goff  = d_GOFF[g];
    const int W     = d_GW[g];
    const int nsel  = d_GN[g];
    const int slot0 = d_GSLOT[g];
    const int r0    = d_GR0[g];

    __shared__ float  y[NPIX];
    __shared__ float  SAT[FM + 1][FM + 1];
    __shared__ float  sc[361];
    __shared__ float  cx0[361], cy0[361], cx1[361], cy1[361];
    __shared__ unsigned char valid[361];
    __shared__ float  warp_s[8];
    __shared__ int    warp_i[8];
    __shared__ int    sel_sh;
    __shared__ int    anyv_sh;

    // ---- sum partials (independent loads; MLP=16) ----
    if (tid < NPIX) {
        float acc = 0.f;
#pragma unroll
        for (int ch = 0; ch < NCHUNK; ch++)
            acc += g_partial[(ch * B + b) * NPIX + tid];
        y[tid] = acc;
    }
    if (tid < FM + 1) { SAT[0][tid] = 0.f; SAT[tid][0] = 0.f; }
    __syncthreads();

    // ---- integral image in float: chains are FADD lat-4, ~60 cyc each pass ----
    if (tid < FM) {
        float r = 0.f;
#pragma unroll
        for (int j = 0; j < FM; j++) {
            r += y[tid * FM + j];
            SAT[tid + 1][j + 1] = r;
        }
    }
    __syncthreads();
    if (tid < FM) {
        float r = 0.f;
#pragma unroll
        for (int i = 1; i <= FM; i++) {
            r += SAT[i][tid + 1];
            SAT[i][tid + 1] = r;
        }
    }
    __syncthreads();

    // ---- window scores + coords for THIS group ----
    for (int w = tid; w < W; w += 256) {
        const int gw = goff + w;
        int r = r0;
#pragma unroll
        for (int k = 1; k < 11; k++) r += (gw >= d_WOFF[k]) & (k > r0);
        const int loc = gw - d_WOFF[r];
        const int rh  = d_RH[r], rw = d_RW[r];
        const int nw  = FM - rw + 1;
        const int i   = loc / nw, j = loc % nw;
        const float s = SAT[i + rh][j + rw] - SAT[i][j + rw]
                      - SAT[i + rh][j]      + SAT[i][j];
        const float sv = s / (float)(rh * rw);
        sc[w]  = sv;
        cx0[w] = (float)(j * 32);
        cy0[w] = (float)(i * 32);
        cx1[w] = (float)((j + rw) * 32 - 1);
        cy1[w] = (float)((i + rh) * 32 - 1);
        valid[w] = 1;
        out[2 * B * 6 + (size_t)b * TW + gw] = sv;   // all_scores
    }
    __syncthreads();

    // ---- greedy NMS for this group ----
    int last = 0;
    for (int step = 0; step < nsel; step++) {
        // per-thread scan (ascending w => first max kept, jnp.argmax semantics)
        float bs = -CUDART_INF_F;
        int   bi = 0x7fffffff;
        for (int w = tid; w < W; w += 256) {
            if (valid[w]) {
                const float s = sc[w];
                if (s > bs) { bs = s; bi = w; }
            }
        }
        // warp reduce (lowest index on ties)
#pragma unroll
        for (int o = 16; o > 0; o >>= 1) {
            const float s2 = __shfl_xor_sync(0xffffffffu, bs, o);
            const int   i2 = __shfl_xor_sync(0xffffffffu, bi, o);
            if (s2 > bs || (s2 == bs && i2 < bi)) { bs = s2; bi = i2; }
        }
        if (lane == 0) { warp_s[wid] = bs; warp_i[wid] = bi; }
        __syncthreads();
        // warp 0 folds the 8 warp winners with shuffles (no extra barrier tree)
        if (wid == 0) {
            float fs = (lane < 8) ? warp_s[lane] : -CUDART_INF_F;
            int   fi = (lane < 8) ? warp_i[lane] : 0x7fffffff;
#pragma unroll
            for (int o = 4; o > 0; o >>= 1) {
                const float s2 = __shfl_xor_sync(0xffffffffu, fs, o);
                const int   i2 = __shfl_xor_sync(0xffffffffu, fi, o);
                if (s2 > fs || (s2 == fs && i2 < fi)) { fs = s2; fi = i2; }
            }
            if (lane == 0) {
                const bool anyv = fs > -CUDART_INF_F;
                anyv_sh = anyv ? 1 : 0;
                sel_sh  = anyv ? fi : last;          // fallback: repeat last
            }
        }
        __syncthreads();
        const int idx = sel_sh;
        if (tid == 0)
            out[(size_t)b * 6 + slot0 + step] = (float)(goff + idx);
        if (tid == 1)
            out[B * 6 + (size_t)b * 6 + slot0 + step] = sc[idx];

        if (anyv_sh) {
            const float sx0 = cx0[idx], sy0 = cy0[idx];
            const float sx1 = cx1[idx], sy1 = cy1[idx];
            const float sarea = (sx1 - sx0 + 1.f) * (sy1 - sy0 + 1.f);
            for (int w = tid; w < W; w += 256) {
                const float lx = fmaxf(cx0[w], sx0);
                const float ly = fmaxf(cy0[w], sy0);
                const float rx = fminf(cx1[w], sx1);
                const float ry = fminf(cy1[w], sy1);
                const float wx = rx - lx + 1.f;
                const float wy = ry - ly + 1.f;
                const float inter = (wx < 0.f || wy < 0.f) ? 0.f : wx * wy;
                const float area  = (cx1[w] - cx0[w] + 1.f) * (cy1[w] - cy0[w] + 1.f);
                const float iou   = inter / (area + sarea - inter);
                if (iou > 0.25f) valid[w] = 0;       // self-IoU=1 clears sel
            }
            if (tid == 0) valid[idx] = 0;
        }
        last = idx;
        __syncthreads();
    }
}

extern "C" void kernel_launch(void* const* d_in, const int* in_sizes, int n_in,
                              void* d_out, int out_size)
{
    const float* x = (const float*)d_in[0];
    float* out = (float*)d_out;
    appm_reduce_kernel<<<dim3(NCHUNK, B), 196>>>(x);
    appm_nms_kernel<<<dim3(B, 3), 256>>>(out);
}